// round 1
// baseline (speedup 1.0000x reference)
#include <cuda_runtime.h>

#define BB 8
#define NN 4096
#define SS 1024
#define KK 32
#define ROWS (BB*SS*KK)   // 262144

// ---------------- scratch ----------------
__device__ float  d_norm[BB*NN];
__device__ float4 d_newxyz[BB*SS];      // x,y,z,||c||^2
__device__ int    d_gidx[ROWS];
__device__ float  d_z0[ROWS*64];
__device__ float  d_z1[ROWS*64];
__device__ float  d_z2[ROWS*128];
__device__ float  d_sum[3*128];
__device__ float  d_sumsq[3*128];
__device__ float  d_scale[3*128];
__device__ float  d_shift[3*128];

__global__ void zero_kernel() {
    int t = threadIdx.x;
    if (t < 384) { d_sum[t] = 0.f; d_sumsq[t] = 0.f; }
}

// ---------------- FPS: 8 blocks, 1024 threads, dist in registers ----------------
__global__ void __launch_bounds__(1024) fps_kernel(const float* __restrict__ xyz,
                                                   float* __restrict__ out) {
    int b = blockIdx.x, tid = threadIdx.x;
    const float* xb = xyz + b * 3 * NN;
    float px[4], py[4], pz[4], dist[4];
#pragma unroll
    for (int j = 0; j < 4; j++) {
        int n = tid + j * 1024;
        px[j] = xb[n]; py[j] = xb[NN + n]; pz[j] = xb[2 * NN + n];
        dist[j] = 1e10f;
        float s2 = __fadd_rn(__fadd_rn(__fmul_rn(px[j], px[j]), __fmul_rn(py[j], py[j])),
                             __fmul_rn(pz[j], pz[j]));
        d_norm[b * NN + n] = s2;
    }
    __shared__ float s_v[32], s_x[32], s_y[32], s_z[32];
    __shared__ int s_i[32];
    __shared__ float bc[3];
    if (tid == 0) { bc[0] = px[0]; bc[1] = py[0]; bc[2] = pz[0]; }
    __syncthreads();
    int lane = tid & 31, warp = tid >> 5;
    for (int it = 0; it < SS; it++) {
        float cx = bc[0], cy = bc[1], cz = bc[2];
        if (tid == 0) {
            out[b * 3 * SS + it]          = cx;
            out[b * 3 * SS + SS + it]     = cy;
            out[b * 3 * SS + 2 * SS + it] = cz;
            float cn = __fadd_rn(__fadd_rn(__fmul_rn(cx, cx), __fmul_rn(cy, cy)),
                                 __fmul_rn(cz, cz));
            d_newxyz[b * SS + it] = make_float4(cx, cy, cz, cn);
        }
        float bv = -1.f, bx = 0.f, by = 0.f, bz = 0.f; int bi = 0;
#pragma unroll
        for (int j = 0; j < 4; j++) {
            float dx = px[j] - cx, dy = py[j] - cy, dz = pz[j] - cz;
            float dd = __fadd_rn(__fadd_rn(__fmul_rn(dx, dx), __fmul_rn(dy, dy)),
                                 __fmul_rn(dz, dz));
            float nd = fminf(dist[j], dd);
            dist[j] = nd;
            if (nd > bv) { bv = nd; bi = tid + j * 1024; bx = px[j]; by = py[j]; bz = pz[j]; }
        }
#pragma unroll
        for (int off = 16; off; off >>= 1) {
            float ov = __shfl_down_sync(0xffffffffu, bv, off);
            int   oi = __shfl_down_sync(0xffffffffu, bi, off);
            float ox = __shfl_down_sync(0xffffffffu, bx, off);
            float oy = __shfl_down_sync(0xffffffffu, by, off);
            float oz = __shfl_down_sync(0xffffffffu, bz, off);
            if (ov > bv || (ov == bv && oi < bi)) { bv = ov; bi = oi; bx = ox; by = oy; bz = oz; }
        }
        if (lane == 0) { s_v[warp] = bv; s_i[warp] = bi; s_x[warp] = bx; s_y[warp] = by; s_z[warp] = bz; }
        __syncthreads();
        if (warp == 0) {
            bv = s_v[lane]; bi = s_i[lane]; bx = s_x[lane]; by = s_y[lane]; bz = s_z[lane];
#pragma unroll
            for (int off = 16; off; off >>= 1) {
                float ov = __shfl_down_sync(0xffffffffu, bv, off);
                int   oi = __shfl_down_sync(0xffffffffu, bi, off);
                float ox = __shfl_down_sync(0xffffffffu, bx, off);
                float oy = __shfl_down_sync(0xffffffffu, by, off);
                float oz = __shfl_down_sync(0xffffffffu, bz, off);
                if (ov > bv || (ov == bv && oi < bi)) { bv = ov; bi = oi; bx = ox; by = oy; bz = oz; }
            }
            if (lane == 0) { bc[0] = bx; bc[1] = by; bc[2] = bz; }
        }
        __syncthreads();
    }
}

// ---------------- ball query: one warp per center ----------------
__global__ void __launch_bounds__(256) bq_kernel(const float* __restrict__ xyz) {
    int gw = (blockIdx.x * blockDim.x + threadIdx.x) >> 5;
    int lane = threadIdx.x & 31;
    int b = gw >> 10, s = gw & 1023;
    float4 c = d_newxyz[b * SS + s];
    const float* xb = xyz + b * 3 * NN;
    const float* nb = d_norm + b * NN;
    int* og = d_gidx + (b * SS + s) * KK;
    int cnt = 0, first = -1;
    for (int base = 0; base < NN; base += 32) {
        int n = base + lane;
        float dot = __fadd_rn(__fadd_rn(__fmul_rn(xb[n], c.x), __fmul_rn(xb[NN + n], c.y)),
                              __fmul_rn(xb[2 * NN + n], c.z));
        float sq = __fadd_rn(c.w, nb[n]) - 2.f * dot;
        bool ok = !(sq > 0.04f);
        unsigned m = __ballot_sync(0xffffffffu, ok);
        if (first < 0 && m) first = base + __ffs(m) - 1;
        if (ok) {
            int slot = cnt + __popc(m & ((1u << lane) - 1u));
            if (slot < KK) og[slot] = n;
        }
        cnt += __popc(m);
        if (cnt >= KK) break;
    }
    if (cnt < KK) {
        for (int k = cnt + lane; k < KK; k += 32) og[k] = first;
    }
}

// ---------------- layer0: gather + linear(6->64) + stats ----------------
__global__ void __launch_bounds__(256) layer0_kernel(const float* __restrict__ xyz,
                                                     const float* __restrict__ pts,
                                                     const float* __restrict__ w0,
                                                     const float* __restrict__ b0) {
    __shared__ float swT[6 * 64];
    __shared__ float sfeat[64 * 6];
    __shared__ float ssum[256], ssq[256];
    int t = threadIdx.x;
    for (int i = t; i < 384; i += 256) { int c = i >> 6, o = i & 63; swT[i] = w0[o * 6 + c]; }
    if (t < 64) {
        int rowg = blockIdx.x * 64 + t;
        int b = rowg >> 15, s = (rowg >> 5) & 1023;
        int n = d_gidx[rowg];
        float4 c4 = d_newxyz[b * SS + s];
        const float* xb = xyz + b * 3 * NN;
        const float* pb = pts + b * 3 * NN;
        sfeat[t * 6 + 0] = xb[n] - c4.x;
        sfeat[t * 6 + 1] = xb[NN + n] - c4.y;
        sfeat[t * 6 + 2] = xb[2 * NN + n] - c4.z;
        sfeat[t * 6 + 3] = pb[n];
        sfeat[t * 6 + 4] = pb[NN + n];
        sfeat[t * 6 + 5] = pb[2 * NN + n];
    }
    __syncthreads();
    int o = t & 63, grp = t >> 6;
    float bias = b0[o];
    float lsum = 0.f, lsq = 0.f;
    int base = blockIdx.x * 64;
#pragma unroll 4
    for (int i = 0; i < 16; i++) {
        int r = grp * 16 + i;
        float acc = bias;
#pragma unroll
        for (int c = 0; c < 6; c++) acc = fmaf(sfeat[r * 6 + c], swT[c * 64 + o], acc);
        d_z0[(base + r) * 64 + o] = acc;
        lsum += acc; lsq = fmaf(acc, acc, lsq);
    }
    ssum[t] = lsum; ssq[t] = lsq; __syncthreads();
    if (t < 64) {
        float a = ssum[t] + ssum[t + 64] + ssum[t + 128] + ssum[t + 192];
        float q = ssq[t] + ssq[t + 64] + ssq[t + 128] + ssq[t + 192];
        atomicAdd(&d_sum[o], a); atomicAdd(&d_sumsq[o], q);
    }
}

__global__ void finalize_kernel(const float* __restrict__ g, const float* __restrict__ be, int l) {
    int o = threadIdx.x;
    float inv = 1.f / (float)ROWS;
    float mean = d_sum[l * 128 + o] * inv;
    float var = d_sumsq[l * 128 + o] * inv - mean * mean;
    float r = rsqrtf(var + 1e-5f);
    float scv = r * g[o];
    d_scale[l * 128 + o] = scv;
    d_shift[l * 128 + o] = fmaf(-mean, scv, be[o]);
}

// ---------------- layer1: BN0+ReLU fused load, linear(64->64) + stats ----------------
__global__ void __launch_bounds__(256) layer1_kernel(const float* __restrict__ w1,
                                                     const float* __restrict__ b1) {
    __shared__ float swT[64 * 64];
    __shared__ float tile[64 * 64];
    __shared__ float sc[64], sh[64];
    __shared__ float ssum[256], ssq[256];
    int t = threadIdx.x;
    if (t < 64) { sc[t] = d_scale[t]; sh[t] = d_shift[t]; }
    for (int i = t; i < 4096; i += 256) { int c = i >> 6, o = i & 63; swT[i] = w1[o * 64 + c]; }
    __syncthreads();
    int base = blockIdx.x * 64;
    for (int i = t; i < 4096; i += 256) {
        int r = i >> 6, c = i & 63;
        float v = d_z0[(base + r) * 64 + c];
        tile[i] = fmaxf(0.f, fmaf(v, sc[c], sh[c]));
    }
    __syncthreads();
    int o = t & 63, grp = t >> 6;
    float bias = b1[o];
    float lsum = 0.f, lsq = 0.f;
    for (int rb = 0; rb < 16; rb += 4) {
        int r0 = grp * 16 + rb;
        float a0 = bias, a1 = bias, a2 = bias, a3 = bias;
#pragma unroll
        for (int c = 0; c < 64; c++) {
            float wv = swT[c * 64 + o];
            a0 = fmaf(tile[(r0 + 0) * 64 + c], wv, a0);
            a1 = fmaf(tile[(r0 + 1) * 64 + c], wv, a1);
            a2 = fmaf(tile[(r0 + 2) * 64 + c], wv, a2);
            a3 = fmaf(tile[(r0 + 3) * 64 + c], wv, a3);
        }
        d_z1[(base + r0 + 0) * 64 + o] = a0;
        d_z1[(base + r0 + 1) * 64 + o] = a1;
        d_z1[(base + r0 + 2) * 64 + o] = a2;
        d_z1[(base + r0 + 3) * 64 + o] = a3;
        lsum += a0 + a1 + a2 + a3;
        lsq = fmaf(a0, a0, lsq); lsq = fmaf(a1, a1, lsq);
        lsq = fmaf(a2, a2, lsq); lsq = fmaf(a3, a3, lsq);
    }
    ssum[t] = lsum; ssq[t] = lsq; __syncthreads();
    if (t < 64) {
        float a = ssum[t] + ssum[t + 64] + ssum[t + 128] + ssum[t + 192];
        float q = ssq[t] + ssq[t + 64] + ssq[t + 128] + ssq[t + 192];
        atomicAdd(&d_sum[128 + o], a); atomicAdd(&d_sumsq[128 + o], q);
    }
}

// ---------------- layer2: BN1+ReLU fused load, linear(64->128) + stats ----------------
__global__ void __launch_bounds__(256) layer2_kernel(const float* __restrict__ w2,
                                                     const float* __restrict__ b2) {
    __shared__ float swT[64 * 128];
    __shared__ float tile[32 * 64];
    __shared__ float sc[64], sh[64];
    __shared__ float ssum[256], ssq[256];
    int t = threadIdx.x;
    if (t < 64) { sc[t] = d_scale[128 + t]; sh[t] = d_shift[128 + t]; }
    for (int i = t; i < 8192; i += 256) { int c = i >> 7, o = i & 127; swT[i] = w2[o * 64 + c]; }
    __syncthreads();
    int base = blockIdx.x * 32;
    for (int i = t; i < 2048; i += 256) {
        int r = i >> 6, c = i & 63;
        float v = d_z1[(base + r) * 64 + c];
        tile[i] = fmaxf(0.f, fmaf(v, sc[c], sh[c]));
    }
    __syncthreads();
    int o = t & 127, grp = t >> 7;
    float bias = b2[o];
    float lsum = 0.f, lsq = 0.f;
    for (int rb = 0; rb < 16; rb += 4) {
        int r0 = grp * 16 + rb;
        float a0 = bias, a1 = bias, a2 = bias, a3 = bias;
#pragma unroll
        for (int c = 0; c < 64; c++) {
            float wv = swT[c * 128 + o];
            a0 = fmaf(tile[(r0 + 0) * 64 + c], wv, a0);
            a1 = fmaf(tile[(r0 + 1) * 64 + c], wv, a1);
            a2 = fmaf(tile[(r0 + 2) * 64 + c], wv, a2);
            a3 = fmaf(tile[(r0 + 3) * 64 + c], wv, a3);
        }
        d_z2[(base + r0 + 0) * 128 + o] = a0;
        d_z2[(base + r0 + 1) * 128 + o] = a1;
        d_z2[(base + r0 + 2) * 128 + o] = a2;
        d_z2[(base + r0 + 3) * 128 + o] = a3;
        lsum += a0 + a1 + a2 + a3;
        lsq = fmaf(a0, a0, lsq); lsq = fmaf(a1, a1, lsq);
        lsq = fmaf(a2, a2, lsq); lsq = fmaf(a3, a3, lsq);
    }
    ssum[t] = lsum; ssq[t] = lsq; __syncthreads();
    if (t < 128) {
        atomicAdd(&d_sum[256 + t], ssum[t] + ssum[t + 128]);
        atomicAdd(&d_sumsq[256 + t], ssq[t] + ssq[t + 128]);
    }
}

// ---------------- BN2+ReLU + maxpool over K + transpose write ----------------
__global__ void __launch_bounds__(256) maxpool_kernel(float* __restrict__ out) {
    __shared__ float stile[32 * 129];
    __shared__ float sc[128], sh[128];
    int t = threadIdx.x;
    if (t < 128) { sc[t] = d_scale[256 + t]; sh[t] = d_shift[256 + t]; }
    __syncthreads();
    int b = blockIdx.x >> 5, s0 = (blockIdx.x & 31) * 32;
    int o = t & 127, grp = t >> 7;
    float scv = sc[o], shv = sh[o];
    for (int i = 0; i < 16; i++) {
        int sl = grp * 16 + i;
        int s = s0 + sl;
        const float* zp = d_z2 + ((b * SS + s) * KK) * 128 + o;
        float m = 0.f;
#pragma unroll 8
        for (int k = 0; k < KK; k++) {
            float y = fmaxf(0.f, fmaf(zp[k * 128], scv, shv));
            m = fmaxf(m, y);
        }
        stile[sl * 129 + o] = m;
    }
    __syncthreads();
    float* ob = out + BB * 3 * SS + b * 128 * SS;
    for (int i = 0; i < 16; i++) {
        int j = t + i * 256;
        int oo = j >> 5, sl = j & 31;
        ob[oo * SS + s0 + sl] = stile[sl * 129 + oo];
    }
}

extern "C" void kernel_launch(void* const* d_in, const int* in_sizes, int n_in,
                              void* d_out, int out_size) {
    (void)in_sizes; (void)n_in; (void)out_size;
    const float* xyz = (const float*)d_in[0];
    const float* pts = (const float*)d_in[1];
    const float* w0 = (const float*)d_in[2];  const float* b0 = (const float*)d_in[3];
    const float* g0 = (const float*)d_in[4];  const float* be0 = (const float*)d_in[5];
    const float* w1 = (const float*)d_in[6];  const float* b1 = (const float*)d_in[7];
    const float* g1 = (const float*)d_in[8];  const float* be1 = (const float*)d_in[9];
    const float* w2 = (const float*)d_in[10]; const float* b2 = (const float*)d_in[11];
    const float* g2 = (const float*)d_in[12]; const float* be2 = (const float*)d_in[13];
    float* out = (float*)d_out;

    zero_kernel<<<1, 384>>>();
    fps_kernel<<<BB, 1024>>>(xyz, out);
    bq_kernel<<<1024, 256>>>(xyz);
    layer0_kernel<<<ROWS / 64, 256>>>(xyz, pts, w0, b0);
    finalize_kernel<<<1, 64>>>(g0, be0, 0);
    layer1_kernel<<<ROWS / 64, 256>>>(w1, b1);
    finalize_kernel<<<1, 64>>>(g1, be1, 1);
    layer2_kernel<<<ROWS / 32, 256>>>(w2, b2);
    finalize_kernel<<<1, 128>>>(g2, be2, 2);
    maxpool_kernel<<<256, 256>>>(out);
}

// round 2
// speedup vs baseline: 1.2415x; 1.2415x over previous
#include <cuda_runtime.h>

#define BB 8
#define NN 4096
#define SS 1024
#define KK 32
#define ROWS (BB*SS*KK)   // 262144

// ---------------- scratch ----------------
__device__ float  d_norm[BB*NN];
__device__ float4 d_newxyz[BB*SS];      // x,y,z,||c||^2
__device__ int    d_gidx[ROWS];
__device__ float  d_z0[ROWS*64];
__device__ float  d_z1[ROWS*64];
__device__ float  d_z2[ROWS*128];
__device__ float  d_sum[3*128];
__device__ float  d_sumsq[3*128];
__device__ float  d_scale[3*128];
__device__ float  d_shift[3*128];

__global__ void zero_kernel() {
    int t = threadIdx.x;
    if (t < 384) { d_sum[t] = 0.f; d_sumsq[t] = 0.f; }
}

__device__ __forceinline__ unsigned redux_max_u32(unsigned v) {
    unsigned r;
    asm volatile("redux.sync.max.u32 %0, %1, 0xffffffff;" : "=r"(r) : "r"(v));
    return r;
}
__device__ __forceinline__ int redux_min_s32(int v) {
    int r;
    asm volatile("redux.sync.min.s32 %0, %1, 0xffffffff;" : "=r"(r) : "r"(v));
    return r;
}

// ---------------- FPS: 8 blocks, 512 threads, 8 pts/thread ----------------
// Per-iteration critical chain: LDS centroid -> 8 dist updates -> 2x redux.sync
// -> STS key -> 1x BAR -> redundant 16-key reduce (broadcast LDS). Double-
// buffered key slots make one barrier per iteration sufficient.
__global__ void __launch_bounds__(512) fps_kernel(const float* __restrict__ xyz,
                                                  float* __restrict__ out) {
    int b = blockIdx.x, tid = threadIdx.x;
    int lane = tid & 31, warp = tid >> 5;
    const float* xb = xyz + b * 3 * NN;
    __shared__ float sx[NN], sy[NN], sz[NN];
    __shared__ unsigned long long s_key[2][16];

    float px[8], py[8], pz[8], dist[8];
    int base = tid * 8;
#pragma unroll
    for (int j = 0; j < 8; j++) {
        int n = base + j;
        float x = xb[n], y = xb[NN + n], z = xb[2 * NN + n];
        px[j] = x; py[j] = y; pz[j] = z; dist[j] = 1e10f;
        sx[n] = x; sy[n] = y; sz[n] = z;
        float s2 = __fadd_rn(__fadd_rn(__fmul_rn(x, x), __fmul_rn(y, y)), __fmul_rn(z, z));
        d_norm[b * NN + n] = s2;
    }
    __syncthreads();

    int widx = 0;
    int buf = 0;
    for (int it = 0; it < SS; it++) {
        float cx = sx[widx], cy = sy[widx], cz = sz[widx];
        if (tid == 0) {
            out[b * 3 * SS + it]          = cx;
            out[b * 3 * SS + SS + it]     = cy;
            out[b * 3 * SS + 2 * SS + it] = cz;
            float cn = __fadd_rn(__fadd_rn(__fmul_rn(cx, cx), __fmul_rn(cy, cy)),
                                 __fmul_rn(cz, cz));
            d_newxyz[b * SS + it] = make_float4(cx, cy, cz, cn);
        }
        float bv = -1.f; int bj = 0;
#pragma unroll
        for (int j = 0; j < 8; j++) {
            float dx = px[j] - cx, dy = py[j] - cy, dz = pz[j] - cz;
            float dd = __fadd_rn(__fadd_rn(__fmul_rn(dx, dx), __fmul_rn(dy, dy)),
                                 __fmul_rn(dz, dz));
            float nd = fminf(dist[j], dd);
            dist[j] = nd;
            if (nd > bv) { bv = nd; bj = j; }  // strict > keeps first (min) index
        }
        unsigned vb = __float_as_uint(bv);            // bv >= 0 so ordering-safe
        unsigned mx = redux_max_u32(vb);
        int cand = (vb == mx) ? (base + bj) : 0x7FFFFFFF;
        int mn = redux_min_s32(cand);
        if (lane == 0)
            s_key[buf][warp] = ((unsigned long long)mx << 32) |
                               (unsigned long long)(0xFFFFFFFFu - (unsigned)mn);
        __syncthreads();
        unsigned long long best = 0ull;
#pragma unroll
        for (int w = 0; w < 16; w++) {
            unsigned long long k = s_key[buf][w];
            best = (k > best) ? k : best;
        }
        widx = (int)(0xFFFFFFFFu - (unsigned)(best & 0xFFFFFFFFull));
        buf ^= 1;
    }
}

// ---------------- ball query: one warp per center ----------------
__global__ void __launch_bounds__(256) bq_kernel(const float* __restrict__ xyz) {
    int gw = (blockIdx.x * blockDim.x + threadIdx.x) >> 5;
    int lane = threadIdx.x & 31;
    int b = gw >> 10, s = gw & 1023;
    float4 c = d_newxyz[b * SS + s];
    const float* xb = xyz + b * 3 * NN;
    const float* nb = d_norm + b * NN;
    int* og = d_gidx + (b * SS + s) * KK;
    int cnt = 0, first = -1;
    for (int base = 0; base < NN; base += 32) {
        int n = base + lane;
        float dot = __fadd_rn(__fadd_rn(__fmul_rn(xb[n], c.x), __fmul_rn(xb[NN + n], c.y)),
                              __fmul_rn(xb[2 * NN + n], c.z));
        float sq = __fadd_rn(c.w, nb[n]) - 2.f * dot;
        bool ok = !(sq > 0.04f);
        unsigned m = __ballot_sync(0xffffffffu, ok);
        if (first < 0 && m) first = base + __ffs(m) - 1;
        if (ok) {
            int slot = cnt + __popc(m & ((1u << lane) - 1u));
            if (slot < KK) og[slot] = n;
        }
        cnt += __popc(m);
        if (cnt >= KK) break;
    }
    if (cnt < KK) {
        for (int k = cnt + lane; k < KK; k += 32) og[k] = first;
    }
}

// ---------------- layer0: gather + linear(6->64) + stats ----------------
__global__ void __launch_bounds__(256) layer0_kernel(const float* __restrict__ xyz,
                                                     const float* __restrict__ pts,
                                                     const float* __restrict__ w0,
                                                     const float* __restrict__ b0) {
    __shared__ float swT[6 * 64];
    __shared__ float sfeat[64 * 6];
    __shared__ float ssum[256], ssq[256];
    int t = threadIdx.x;
    for (int i = t; i < 384; i += 256) { int c = i >> 6, o = i & 63; swT[i] = w0[o * 6 + c]; }
    if (t < 64) {
        int rowg = blockIdx.x * 64 + t;
        int b = rowg >> 15, s = (rowg >> 5) & 1023;
        int n = d_gidx[rowg];
        float4 c4 = d_newxyz[b * SS + s];
        const float* xb = xyz + b * 3 * NN;
        const float* pb = pts + b * 3 * NN;
        sfeat[t * 6 + 0] = xb[n] - c4.x;
        sfeat[t * 6 + 1] = xb[NN + n] - c4.y;
        sfeat[t * 6 + 2] = xb[2 * NN + n] - c4.z;
        sfeat[t * 6 + 3] = pb[n];
        sfeat[t * 6 + 4] = pb[NN + n];
        sfeat[t * 6 + 5] = pb[2 * NN + n];
    }
    __syncthreads();
    int o = t & 63, grp = t >> 6;
    float bias = b0[o];
    float lsum = 0.f, lsq = 0.f;
    int base = blockIdx.x * 64;
#pragma unroll 4
    for (int i = 0; i < 16; i++) {
        int r = grp * 16 + i;
        float acc = bias;
#pragma unroll
        for (int c = 0; c < 6; c++) acc = fmaf(sfeat[r * 6 + c], swT[c * 64 + o], acc);
        d_z0[(base + r) * 64 + o] = acc;
        lsum += acc; lsq = fmaf(acc, acc, lsq);
    }
    ssum[t] = lsum; ssq[t] = lsq; __syncthreads();
    if (t < 64) {
        float a = ssum[t] + ssum[t + 64] + ssum[t + 128] + ssum[t + 192];
        float q = ssq[t] + ssq[t + 64] + ssq[t + 128] + ssq[t + 192];
        atomicAdd(&d_sum[o], a); atomicAdd(&d_sumsq[o], q);
    }
}

__global__ void finalize_kernel(const float* __restrict__ g, const float* __restrict__ be, int l) {
    int o = threadIdx.x;
    float inv = 1.f / (float)ROWS;
    float mean = d_sum[l * 128 + o] * inv;
    float var = d_sumsq[l * 128 + o] * inv - mean * mean;
    float r = rsqrtf(var + 1e-5f);
    float scv = r * g[o];
    d_scale[l * 128 + o] = scv;
    d_shift[l * 128 + o] = fmaf(-mean, scv, be[o]);
}

// ---------------- layer1: BN0+ReLU fused load, linear(64->64) + stats ----------------
__global__ void __launch_bounds__(256) layer1_kernel(const float* __restrict__ w1,
                                                     const float* __restrict__ b1) {
    __shared__ float swT[64 * 64];
    __shared__ float tile[64 * 64];
    __shared__ float sc[64], sh[64];
    __shared__ float ssum[256], ssq[256];
    int t = threadIdx.x;
    if (t < 64) { sc[t] = d_scale[t]; sh[t] = d_shift[t]; }
    for (int i = t; i < 4096; i += 256) { int c = i >> 6, o = i & 63; swT[i] = w1[o * 64 + c]; }
    __syncthreads();
    int base = blockIdx.x * 64;
    for (int i = t; i < 4096; i += 256) {
        int r = i >> 6, c = i & 63;
        float v = d_z0[(base + r) * 64 + c];
        tile[i] = fmaxf(0.f, fmaf(v, sc[c], sh[c]));
    }
    __syncthreads();
    int o = t & 63, grp = t >> 6;
    float bias = b1[o];
    float lsum = 0.f, lsq = 0.f;
    for (int rb = 0; rb < 16; rb += 4) {
        int r0 = grp * 16 + rb;
        float a0 = bias, a1 = bias, a2 = bias, a3 = bias;
#pragma unroll
        for (int c = 0; c < 64; c++) {
            float wv = swT[c * 64 + o];
            a0 = fmaf(tile[(r0 + 0) * 64 + c], wv, a0);
            a1 = fmaf(tile[(r0 + 1) * 64 + c], wv, a1);
            a2 = fmaf(tile[(r0 + 2) * 64 + c], wv, a2);
            a3 = fmaf(tile[(r0 + 3) * 64 + c], wv, a3);
        }
        d_z1[(base + r0 + 0) * 64 + o] = a0;
        d_z1[(base + r0 + 1) * 64 + o] = a1;
        d_z1[(base + r0 + 2) * 64 + o] = a2;
        d_z1[(base + r0 + 3) * 64 + o] = a3;
        lsum += a0 + a1 + a2 + a3;
        lsq = fmaf(a0, a0, lsq); lsq = fmaf(a1, a1, lsq);
        lsq = fmaf(a2, a2, lsq); lsq = fmaf(a3, a3, lsq);
    }
    ssum[t] = lsum; ssq[t] = lsq; __syncthreads();
    if (t < 64) {
        float a = ssum[t] + ssum[t + 64] + ssum[t + 128] + ssum[t + 192];
        float q = ssq[t] + ssq[t + 64] + ssq[t + 128] + ssq[t + 192];
        atomicAdd(&d_sum[128 + o], a); atomicAdd(&d_sumsq[128 + o], q);
    }
}

// ---------------- layer2: BN1+ReLU fused load, linear(64->128) + stats ----------------
__global__ void __launch_bounds__(256) layer2_kernel(const float* __restrict__ w2,
                                                     const float* __restrict__ b2) {
    __shared__ float swT[64 * 128];
    __shared__ float tile[32 * 64];
    __shared__ float sc[64], sh[64];
    __shared__ float ssum[256], ssq[256];
    int t = threadIdx.x;
    if (t < 64) { sc[t] = d_scale[128 + t]; sh[t] = d_shift[128 + t]; }
    for (int i = t; i < 8192; i += 256) { int c = i >> 7, o = i & 127; swT[i] = w2[o * 64 + c]; }
    __syncthreads();
    int base = blockIdx.x * 32;
    for (int i = t; i < 2048; i += 256) {
        int r = i >> 6, c = i & 63;
        float v = d_z1[(base + r) * 64 + c];
        tile[i] = fmaxf(0.f, fmaf(v, sc[c], sh[c]));
    }
    __syncthreads();
    int o = t & 127, grp = t >> 7;
    float bias = b2[o];
    float lsum = 0.f, lsq = 0.f;
    for (int rb = 0; rb < 16; rb += 4) {
        int r0 = grp * 16 + rb;
        float a0 = bias, a1 = bias, a2 = bias, a3 = bias;
#pragma unroll
        for (int c = 0; c < 64; c++) {
            float wv = swT[c * 128 + o];
            a0 = fmaf(tile[(r0 + 0) * 64 + c], wv, a0);
            a1 = fmaf(tile[(r0 + 1) * 64 + c], wv, a1);
            a2 = fmaf(tile[(r0 + 2) * 64 + c], wv, a2);
            a3 = fmaf(tile[(r0 + 3) * 64 + c], wv, a3);
        }
        d_z2[(base + r0 + 0) * 128 + o] = a0;
        d_z2[(base + r0 + 1) * 128 + o] = a1;
        d_z2[(base + r0 + 2) * 128 + o] = a2;
        d_z2[(base + r0 + 3) * 128 + o] = a3;
        lsum += a0 + a1 + a2 + a3;
        lsq = fmaf(a0, a0, lsq); lsq = fmaf(a1, a1, lsq);
        lsq = fmaf(a2, a2, lsq); lsq = fmaf(a3, a3, lsq);
    }
    ssum[t] = lsum; ssq[t] = lsq; __syncthreads();
    if (t < 128) {
        atomicAdd(&d_sum[256 + t], ssum[t] + ssum[t + 128]);
        atomicAdd(&d_sumsq[256 + t], ssq[t] + ssq[t + 128]);
    }
}

// ---------------- BN2+ReLU + maxpool over K + transpose write ----------------
__global__ void __launch_bounds__(256) maxpool_kernel(float* __restrict__ out) {
    __shared__ float stile[32 * 129];
    __shared__ float sc[128], sh[128];
    int t = threadIdx.x;
    if (t < 128) { sc[t] = d_scale[256 + t]; sh[t] = d_shift[256 + t]; }
    __syncthreads();
    int b = blockIdx.x >> 5, s0 = (blockIdx.x & 31) * 32;
    int o = t & 127, grp = t >> 7;
    float scv = sc[o], shv = sh[o];
    for (int i = 0; i < 16; i++) {
        int sl = grp * 16 + i;
        int s = s0 + sl;
        const float* zp = d_z2 + ((b * SS + s) * KK) * 128 + o;
        float m = 0.f;
#pragma unroll 8
        for (int k = 0; k < KK; k++) {
            float y = fmaxf(0.f, fmaf(zp[k * 128], scv, shv));
            m = fmaxf(m, y);
        }
        stile[sl * 129 + o] = m;
    }
    __syncthreads();
    float* ob = out + BB * 3 * SS + b * 128 * SS;
    for (int i = 0; i < 16; i++) {
        int j = t + i * 256;
        int oo = j >> 5, sl = j & 31;
        ob[oo * SS + s0 + sl] = stile[sl * 129 + oo];
    }
}

extern "C" void kernel_launch(void* const* d_in, const int* in_sizes, int n_in,
                              void* d_out, int out_size) {
    (void)in_sizes; (void)n_in; (void)out_size;
    const float* xyz = (const float*)d_in[0];
    const float* pts = (const float*)d_in[1];
    const float* w0 = (const float*)d_in[2];  const float* b0 = (const float*)d_in[3];
    const float* g0 = (const float*)d_in[4];  const float* be0 = (const float*)d_in[5];
    const float* w1 = (const float*)d_in[6];  const float* b1 = (const float*)d_in[7];
    const float* g1 = (const float*)d_in[8];  const float* be1 = (const float*)d_in[9];
    const float* w2 = (const float*)d_in[10]; const float* b2 = (const float*)d_in[11];
    const float* g2 = (const float*)d_in[12]; const float* be2 = (const float*)d_in[13];
    float* out = (float*)d_out;

    zero_kernel<<<1, 384>>>();
    fps_kernel<<<BB, 512>>>(xyz, out);
    bq_kernel<<<1024, 256>>>(xyz);
    layer0_kernel<<<ROWS / 64, 256>>>(xyz, pts, w0, b0);
    finalize_kernel<<<1, 64>>>(g0, be0, 0);
    layer1_kernel<<<ROWS / 64, 256>>>(w1, b1);
    finalize_kernel<<<1, 64>>>(g1, be1, 1);
    layer2_kernel<<<ROWS / 32, 256>>>(w2, b2);
    finalize_kernel<<<1, 128>>>(g2, be2, 2);
    maxpool_kernel<<<256, 256>>>(out);
}

// round 3
// speedup vs baseline: 2.2279x; 1.7946x over previous
#include <cuda_runtime.h>

#define BB 8
#define NN 4096
#define SS 1024
#define KK 32
#define ROWS (BB*SS*KK)   // 262144

// ---------------- scratch ----------------
__device__ float  d_norm[BB*NN];
__device__ float4 d_newxyz[BB*SS];      // x,y,z,||c||^2
__device__ int    d_gidx[ROWS];
__device__ float  d_z0[ROWS*64];
__device__ float  d_z1[ROWS*64];
__device__ float  d_z2[ROWS*128];
__device__ float  d_sum[3*128];
__device__ float  d_sumsq[3*128];
__device__ float  d_scale[3*128];
__device__ float  d_shift[3*128];

__global__ void zero_kernel() {
    int t = threadIdx.x;
    if (t < 384) { d_sum[t] = 0.f; d_sumsq[t] = 0.f; }
}

__device__ __forceinline__ unsigned redux_max_u32(unsigned v) {
    unsigned r;
    asm volatile("redux.sync.max.u32 %0, %1, 0xffffffff;" : "=r"(r) : "r"(v));
    return r;
}
__device__ __forceinline__ int redux_min_s32(int v) {
    int r;
    asm volatile("redux.sync.min.s32 %0, %1, 0xffffffff;" : "=r"(r) : "r"(v));
    return r;
}

// ---------------- FPS: 8 blocks, 128 threads (4 warps), 32 pts/thread ----------------
__global__ void __launch_bounds__(128) fps_kernel(const float* __restrict__ xyz,
                                                  float* __restrict__ out) {
    int b = blockIdx.x, tid = threadIdx.x;
    int lane = tid & 31, warp = tid >> 5;
    const float* xb = xyz + b * 3 * NN;
    __shared__ float sx[NN], sy[NN], sz[NN];
    __shared__ unsigned long long s_key[2][4];

    float px[32], py[32], pz[32], dist[32];
#pragma unroll
    for (int j = 0; j < 32; j++) {
        int n = tid + j * 128;
        float x = xb[n], y = xb[NN + n], z = xb[2 * NN + n];
        px[j] = x; py[j] = y; pz[j] = z; dist[j] = 1e10f;
        sx[n] = x; sy[n] = y; sz[n] = z;
        d_norm[b * NN + n] = __fadd_rn(__fadd_rn(__fmul_rn(x, x), __fmul_rn(y, y)),
                                       __fmul_rn(z, z));
    }
    __syncthreads();

    float cx = sx[0], cy = sy[0], cz = sz[0];
    int buf = 0;
    for (int it = 0; it < SS; it++) {
        if (tid == 0) {
            out[b * 3 * SS + it]          = cx;
            out[b * 3 * SS + SS + it]     = cy;
            out[b * 3 * SS + 2 * SS + it] = cz;
            float cn = __fadd_rn(__fadd_rn(__fmul_rn(cx, cx), __fmul_rn(cy, cy)),
                                 __fmul_rn(cz, cz));
            d_newxyz[b * SS + it] = make_float4(cx, cy, cz, cn);
        }
        // 4 independent argmax chains of 8, merged in order (keeps first index)
        float bva[4]; int bja[4];
#pragma unroll
        for (int cch = 0; cch < 4; cch++) {
            bva[cch] = -1.f; bja[cch] = 0;
#pragma unroll
            for (int u = 0; u < 8; u++) {
                int j = cch * 8 + u;
                float dx = px[j] - cx, dy = py[j] - cy, dz = pz[j] - cz;
                float dd = __fadd_rn(__fadd_rn(__fmul_rn(dx, dx), __fmul_rn(dy, dy)),
                                     __fmul_rn(dz, dz));
                float nd = fminf(dist[j], dd);
                dist[j] = nd;
                if (nd > bva[cch]) { bva[cch] = nd; bja[cch] = j; }
            }
        }
        float bv = bva[0]; int bj = bja[0];
#pragma unroll
        for (int cch = 1; cch < 4; cch++)
            if (bva[cch] > bv) { bv = bva[cch]; bj = bja[cch]; }

        unsigned vb = __float_as_uint(bv);
        unsigned mx = redux_max_u32(vb);
        int cand = (vb == mx) ? (tid + bj * 128) : 0x7FFFFFFF;
        int mn = redux_min_s32(cand);
        if (lane == 0)
            s_key[buf][warp] = ((unsigned long long)mx << 32) |
                               (unsigned long long)(0xFFFFFFFFu - (unsigned)mn);
        __syncthreads();
        unsigned long long k0 = s_key[buf][0], k1 = s_key[buf][1];
        unsigned long long k2 = s_key[buf][2], k3 = s_key[buf][3];
        unsigned long long ba = (k0 > k1) ? k0 : k1;
        unsigned long long bb = (k2 > k3) ? k2 : k3;
        unsigned long long best = (ba > bb) ? ba : bb;
        int widx = (int)(0xFFFFFFFFu - (unsigned)(best & 0xFFFFFFFFull));
        cx = sx[widx]; cy = sy[widx]; cz = sz[widx];
        buf ^= 1;
    }
}

// ---------------- ball query: one warp per center ----------------
__global__ void __launch_bounds__(256) bq_kernel(const float* __restrict__ xyz) {
    int gw = (blockIdx.x * blockDim.x + threadIdx.x) >> 5;
    int lane = threadIdx.x & 31;
    int b = gw >> 10, s = gw & 1023;
    float4 c = d_newxyz[b * SS + s];
    const float* xb = xyz + b * 3 * NN;
    const float* nb = d_norm + b * NN;
    int* og = d_gidx + (b * SS + s) * KK;
    int cnt = 0, first = -1;
    for (int base = 0; base < NN; base += 32) {
        int n = base + lane;
        float dot = __fadd_rn(__fadd_rn(__fmul_rn(xb[n], c.x), __fmul_rn(xb[NN + n], c.y)),
                              __fmul_rn(xb[2 * NN + n], c.z));
        float sq = __fadd_rn(c.w, nb[n]) - 2.f * dot;
        bool ok = !(sq > 0.04f);
        unsigned m = __ballot_sync(0xffffffffu, ok);
        if (first < 0 && m) first = base + __ffs(m) - 1;
        if (ok) {
            int slot = cnt + __popc(m & ((1u << lane) - 1u));
            if (slot < KK) og[slot] = n;
        }
        cnt += __popc(m);
        if (cnt >= KK) break;
    }
    if (cnt < KK) {
        for (int k = cnt + lane; k < KK; k += 32) og[k] = first;
    }
}

// ---------------- layer0: gather + linear(6->64) + stats ----------------
__global__ void __launch_bounds__(256) layer0_kernel(const float* __restrict__ xyz,
                                                     const float* __restrict__ pts,
                                                     const float* __restrict__ w0,
                                                     const float* __restrict__ b0) {
    __shared__ float swT[6 * 64];
    __shared__ float sfeat[64 * 6];
    __shared__ float ssum[256], ssq[256];
    int t = threadIdx.x;
    for (int i = t; i < 384; i += 256) { int c = i >> 6, o = i & 63; swT[i] = w0[o * 6 + c]; }
    if (t < 64) {
        int rowg = blockIdx.x * 64 + t;
        int b = rowg >> 15, s = (rowg >> 5) & 1023;
        int n = d_gidx[rowg];
        float4 c4 = d_newxyz[b * SS + s];
        const float* xb = xyz + b * 3 * NN;
        const float* pb = pts + b * 3 * NN;
        sfeat[t * 6 + 0] = xb[n] - c4.x;
        sfeat[t * 6 + 1] = xb[NN + n] - c4.y;
        sfeat[t * 6 + 2] = xb[2 * NN + n] - c4.z;
        sfeat[t * 6 + 3] = pb[n];
        sfeat[t * 6 + 4] = pb[NN + n];
        sfeat[t * 6 + 5] = pb[2 * NN + n];
    }
    __syncthreads();
    int o = t & 63, grp = t >> 6;
    float bias = b0[o];
    float lsum = 0.f, lsq = 0.f;
    int base = blockIdx.x * 64;
#pragma unroll 4
    for (int i = 0; i < 16; i++) {
        int r = grp * 16 + i;
        float acc = bias;
#pragma unroll
        for (int c = 0; c < 6; c++) acc = fmaf(sfeat[r * 6 + c], swT[c * 64 + o], acc);
        d_z0[(base + r) * 64 + o] = acc;
        lsum += acc; lsq = fmaf(acc, acc, lsq);
    }
    ssum[t] = lsum; ssq[t] = lsq; __syncthreads();
    if (t < 64) {
        float a = ssum[t] + ssum[t + 64] + ssum[t + 128] + ssum[t + 192];
        float q = ssq[t] + ssq[t + 64] + ssq[t + 128] + ssq[t + 192];
        atomicAdd(&d_sum[o], a); atomicAdd(&d_sumsq[o], q);
    }
}

__global__ void finalize_kernel(const float* __restrict__ g, const float* __restrict__ be, int l) {
    int o = threadIdx.x;
    float inv = 1.f / (float)ROWS;
    float mean = d_sum[l * 128 + o] * inv;
    float var = d_sumsq[l * 128 + o] * inv - mean * mean;
    float r = rsqrtf(var + 1e-5f);
    float scv = r * g[o];
    d_scale[l * 128 + o] = scv;
    d_shift[l * 128 + o] = fmaf(-mean, scv, be[o]);
}

// ---------------- layer1: 128 threads, 128 rows x 64 outs, 8x8 per thread ----------------
#define T1PAD 68
__global__ void __launch_bounds__(128) layer1_kernel(const float* __restrict__ w1,
                                                     const float* __restrict__ b1) {
    __shared__ float swT[64 * 65];
    __shared__ float tile[128 * T1PAD];
    __shared__ float s_sumP[64], s_sqP[64];
    int t = threadIdx.x;
    if (t < 64) { s_sumP[t] = 0.f; s_sqP[t] = 0.f; }
    // weights transposed: swT[c*65+o] = w1[o*64+c], coalesced global read
    for (int i = t; i < 4096; i += 128) {
        int o = i >> 6, c = i & 63;
        swT[c * 65 + o] = w1[i];
    }
    // tile fill with BN0+ReLU: per-thread fixed 4 channels
    int base = blockIdx.x * 128;
    int c0 = (t * 4) & 63;
    float sc0 = d_scale[c0], sc1 = d_scale[c0 + 1], sc2 = d_scale[c0 + 2], sc3 = d_scale[c0 + 3];
    float sh0 = d_shift[c0], sh1 = d_shift[c0 + 1], sh2 = d_shift[c0 + 2], sh3 = d_shift[c0 + 3];
#pragma unroll
    for (int k = 0; k < 16; k++) {
        int r = (t >> 4) + 8 * k;
        const float4 v = *(const float4*)(d_z0 + (size_t)(base + r) * 64 + c0);
        float4 w;
        w.x = fmaxf(0.f, fmaf(v.x, sc0, sh0));
        w.y = fmaxf(0.f, fmaf(v.y, sc1, sh1));
        w.z = fmaxf(0.f, fmaf(v.z, sc2, sh2));
        w.w = fmaxf(0.f, fmaf(v.w, sc3, sh3));
        *(float4*)(tile + r * T1PAD + c0) = w;
    }
    int rg = t >> 3;   // 0..15
    int og = t & 7;    // 0..7, outs o = og + 8k
    float bias[8];
#pragma unroll
    for (int k = 0; k < 8; k++) bias[k] = b1[og + 8 * k];
    float acc[8][8];
#pragma unroll
    for (int i = 0; i < 8; i++)
#pragma unroll
        for (int k = 0; k < 8; k++) acc[i][k] = bias[k];
    __syncthreads();
#pragma unroll 4
    for (int c = 0; c < 64; c++) {
        float av[8], wv[8];
#pragma unroll
        for (int i = 0; i < 8; i++) av[i] = tile[(rg + 16 * i) * T1PAD + c];
#pragma unroll
        for (int k = 0; k < 8; k++) wv[k] = swT[c * 65 + og + 8 * k];
#pragma unroll
        for (int i = 0; i < 8; i++)
#pragma unroll
            for (int k = 0; k < 8; k++) acc[i][k] = fmaf(av[i], wv[k], acc[i][k]);
    }
    // stores + stats
#pragma unroll
    for (int i = 0; i < 8; i++) {
        int r = base + rg + 16 * i;
#pragma unroll
        for (int k = 0; k < 8; k++) d_z1[(size_t)r * 64 + og + 8 * k] = acc[i][k];
    }
#pragma unroll
    for (int k = 0; k < 8; k++) {
        float s = 0.f, q = 0.f;
#pragma unroll
        for (int i = 0; i < 8; i++) { s += acc[i][k]; q = fmaf(acc[i][k], acc[i][k], q); }
        atomicAdd(&s_sumP[og + 8 * k], s);
        atomicAdd(&s_sqP[og + 8 * k], q);
    }
    __syncthreads();
    if (t < 64) {
        atomicAdd(&d_sum[128 + t], s_sumP[t]);
        atomicAdd(&d_sumsq[128 + t], s_sqP[t]);
    }
}

// ---------------- layer2: 256 threads, 128 rows x 128 outs, 8x8 per thread ----------------
#define T2PAD 68
__global__ void __launch_bounds__(256) layer2_kernel(const float* __restrict__ w2,
                                                     const float* __restrict__ b2) {
    __shared__ float swT[64 * 129];
    __shared__ float tile[128 * T2PAD];
    __shared__ float s_sumP[128], s_sqP[128];
    int t = threadIdx.x;
    if (t < 128) { s_sumP[t] = 0.f; s_sqP[t] = 0.f; }
    // weights transposed: swT[c*129+o] = w2[o*64+c]
    for (int i = t; i < 8192; i += 256) {
        int o = i >> 6, c = i & 63;
        swT[c * 129 + o] = w2[i];
    }
    int base = blockIdx.x * 128;
    int c0 = (t * 4) & 63;
    float sc0 = d_scale[128 + c0], sc1 = d_scale[128 + c0 + 1];
    float sc2 = d_scale[128 + c0 + 2], sc3 = d_scale[128 + c0 + 3];
    float sh0 = d_shift[128 + c0], sh1 = d_shift[128 + c0 + 1];
    float sh2 = d_shift[128 + c0 + 2], sh3 = d_shift[128 + c0 + 3];
#pragma unroll
    for (int k = 0; k < 8; k++) {
        int r = (t >> 4) + 16 * k;
        const float4 v = *(const float4*)(d_z1 + (size_t)(base + r) * 64 + c0);
        float4 w;
        w.x = fmaxf(0.f, fmaf(v.x, sc0, sh0));
        w.y = fmaxf(0.f, fmaf(v.y, sc1, sh1));
        w.z = fmaxf(0.f, fmaf(v.z, sc2, sh2));
        w.w = fmaxf(0.f, fmaf(v.w, sc3, sh3));
        *(float4*)(tile + r * T2PAD + c0) = w;
    }
    int rg = t >> 4;    // 0..15
    int og = t & 15;    // 0..15, outs o = og + 16k
    float bias[8];
#pragma unroll
    for (int k = 0; k < 8; k++) bias[k] = b2[og + 16 * k];
    float acc[8][8];
#pragma unroll
    for (int i = 0; i < 8; i++)
#pragma unroll
        for (int k = 0; k < 8; k++) acc[i][k] = bias[k];
    __syncthreads();
#pragma unroll 4
    for (int c = 0; c < 64; c++) {
        float av[8], wv[8];
#pragma unroll
        for (int i = 0; i < 8; i++) av[i] = tile[(rg + 16 * i) * T2PAD + c];
#pragma unroll
        for (int k = 0; k < 8; k++) wv[k] = swT[c * 129 + og + 16 * k];
#pragma unroll
        for (int i = 0; i < 8; i++)
#pragma unroll
            for (int k = 0; k < 8; k++) acc[i][k] = fmaf(av[i], wv[k], acc[i][k]);
    }
#pragma unroll
    for (int i = 0; i < 8; i++) {
        int r = base + rg + 16 * i;
#pragma unroll
        for (int k = 0; k < 8; k++) d_z2[(size_t)r * 128 + og + 16 * k] = acc[i][k];
    }
#pragma unroll
    for (int k = 0; k < 8; k++) {
        float s = 0.f, q = 0.f;
#pragma unroll
        for (int i = 0; i < 8; i++) { s += acc[i][k]; q = fmaf(acc[i][k], acc[i][k], q); }
        atomicAdd(&s_sumP[og + 16 * k], s);
        atomicAdd(&s_sqP[og + 16 * k], q);
    }
    __syncthreads();
    if (t < 128) {
        atomicAdd(&d_sum[256 + t], s_sumP[t]);
        atomicAdd(&d_sumsq[256 + t], s_sqP[t]);
    }
}

// ---------------- BN2+ReLU + maxpool over K + transpose write ----------------
__global__ void __launch_bounds__(256) maxpool_kernel(float* __restrict__ out) {
    __shared__ float stile[32 * 129];
    __shared__ float sc[128], sh[128];
    int t = threadIdx.x;
    if (t < 128) { sc[t] = d_scale[256 + t]; sh[t] = d_shift[256 + t]; }
    __syncthreads();
    int b = blockIdx.x >> 5, s0 = (blockIdx.x & 31) * 32;
    int o = t & 127, grp = t >> 7;
    float scv = sc[o], shv = sh[o];
    for (int i = 0; i < 16; i++) {
        int sl = grp * 16 + i;
        int s = s0 + sl;
        const float* zp = d_z2 + ((size_t)(b * SS + s) * KK) * 128 + o;
        float m = 0.f;
#pragma unroll 8
        for (int k = 0; k < KK; k++) {
            float y = fmaxf(0.f, fmaf(zp[k * 128], scv, shv));
            m = fmaxf(m, y);
        }
        stile[sl * 129 + o] = m;
    }
    __syncthreads();
    float* ob = out + BB * 3 * SS + b * 128 * SS;
    for (int i = 0; i < 16; i++) {
        int j = t + i * 256;
        int oo = j >> 5, sl = j & 31;
        ob[oo * SS + s0 + sl] = stile[sl * 129 + oo];
    }
}

extern "C" void kernel_launch(void* const* d_in, const int* in_sizes, int n_in,
                              void* d_out, int out_size) {
    (void)in_sizes; (void)n_in; (void)out_size;
    const float* xyz = (const float*)d_in[0];
    const float* pts = (const float*)d_in[1];
    const float* w0 = (const float*)d_in[2];  const float* b0 = (const float*)d_in[3];
    const float* g0 = (const float*)d_in[4];  const float* be0 = (const float*)d_in[5];
    const float* w1 = (const float*)d_in[6];  const float* b1 = (const float*)d_in[7];
    const float* g1 = (const float*)d_in[8];  const float* be1 = (const float*)d_in[9];
    const float* w2 = (const float*)d_in[10]; const float* b2 = (const float*)d_in[11];
    const float* g2 = (const float*)d_in[12]; const float* be2 = (const float*)d_in[13];
    float* out = (float*)d_out;

    zero_kernel<<<1, 384>>>();
    fps_kernel<<<BB, 128>>>(xyz, out);
    bq_kernel<<<1024, 256>>>(xyz);
    layer0_kernel<<<ROWS / 64, 256>>>(xyz, pts, w0, b0);
    finalize_kernel<<<1, 64>>>(g0, be0, 0);
    layer1_kernel<<<ROWS / 128, 128>>>(w1, b1);
    finalize_kernel<<<1, 64>>>(g1, be1, 1);
    layer2_kernel<<<ROWS / 128, 256>>>(w2, b2);
    finalize_kernel<<<1, 128>>>(g2, be2, 2);
    maxpool_kernel<<<256, 256>>>(out);
}

// round 4
// speedup vs baseline: 2.4921x; 1.1186x over previous
#include <cuda_runtime.h>

#define BB 8
#define NN 4096
#define SS 1024
#define KK 32
#define ROWS (BB*SS*KK)   // 262144

// ---------------- scratch ----------------
__device__ float  d_norm[BB*NN];
__device__ float4 d_newxyz[BB*SS];      // x,y,z,||c||^2
__device__ int    d_gidx[ROWS];
__device__ float  d_z0[ROWS*64];
__device__ float  d_z1[ROWS*64];
__device__ float  d_sum[3*128];
__device__ float  d_sumsq[3*128];
__device__ float  d_scale[3*128];
__device__ float  d_shift[3*128];

__global__ void zero_kernel() {
    int t = threadIdx.x;
    if (t < 384) { d_sum[t] = 0.f; d_sumsq[t] = 0.f; }
}

__device__ __forceinline__ unsigned redux_max_u32(unsigned v) {
    unsigned r;
    asm volatile("redux.sync.max.u32 %0, %1, 0xffffffff;" : "=r"(r) : "r"(v));
    return r;
}
__device__ __forceinline__ int redux_min_s32(int v) {
    int r;
    asm volatile("redux.sync.min.s32 %0, %1, 0xffffffff;" : "=r"(r) : "r"(v));
    return r;
}
__device__ __forceinline__ float tf32r(float x) {
    unsigned u;
    asm("cvt.rna.tf32.f32 %0, %1;" : "=r"(u) : "f"(x));
    return __uint_as_float(u);
}
__device__ __forceinline__ void mma_tf32(float& d0, float& d1, float& d2, float& d3,
                                         unsigned a0, unsigned a1, unsigned a2, unsigned a3,
                                         unsigned b0, unsigned b1) {
    asm volatile("mma.sync.aligned.m16n8k8.row.col.f32.tf32.tf32.f32 "
                 "{%0,%1,%2,%3}, {%4,%5,%6,%7}, {%8,%9}, {%0,%1,%2,%3};"
                 : "+f"(d0), "+f"(d1), "+f"(d2), "+f"(d3)
                 : "r"(a0), "r"(a1), "r"(a2), "r"(a3), "r"(b0), "r"(b1));
}

// ---------------- FPS: 8 blocks, 128 threads (4 warps), 32 pts/thread ----------------
__global__ void __launch_bounds__(128) fps_kernel(const float* __restrict__ xyz,
                                                  float* __restrict__ out) {
    int b = blockIdx.x, tid = threadIdx.x;
    int lane = tid & 31, warp = tid >> 5;
    const float* xb = xyz + b * 3 * NN;
    __shared__ float sx[NN], sy[NN], sz[NN];
    __shared__ unsigned long long s_key[2][4];

    float px[32], py[32], pz[32], dist[32];
#pragma unroll
    for (int j = 0; j < 32; j++) {
        int n = tid + j * 128;
        float x = xb[n], y = xb[NN + n], z = xb[2 * NN + n];
        px[j] = x; py[j] = y; pz[j] = z; dist[j] = 1e10f;
        sx[n] = x; sy[n] = y; sz[n] = z;
        d_norm[b * NN + n] = __fadd_rn(__fadd_rn(__fmul_rn(x, x), __fmul_rn(y, y)),
                                       __fmul_rn(z, z));
    }
    __syncthreads();

    float cx = sx[0], cy = sy[0], cz = sz[0];
    int buf = 0;
    for (int it = 0; it < SS; it++) {
        if (tid == 0) {
            out[b * 3 * SS + it]          = cx;
            out[b * 3 * SS + SS + it]     = cy;
            out[b * 3 * SS + 2 * SS + it] = cz;
            float cn = __fadd_rn(__fadd_rn(__fmul_rn(cx, cx), __fmul_rn(cy, cy)),
                                 __fmul_rn(cz, cz));
            d_newxyz[b * SS + it] = make_float4(cx, cy, cz, cn);
        }
        float bva[4]; int bja[4];
#pragma unroll
        for (int cch = 0; cch < 4; cch++) {
            bva[cch] = -1.f; bja[cch] = 0;
#pragma unroll
            for (int u = 0; u < 8; u++) {
                int j = cch * 8 + u;
                float dx = px[j] - cx, dy = py[j] - cy, dz = pz[j] - cz;
                float dd = __fadd_rn(__fadd_rn(__fmul_rn(dx, dx), __fmul_rn(dy, dy)),
                                     __fmul_rn(dz, dz));
                float nd = fminf(dist[j], dd);
                dist[j] = nd;
                if (nd > bva[cch]) { bva[cch] = nd; bja[cch] = j; }
            }
        }
        float bv = bva[0]; int bj = bja[0];
#pragma unroll
        for (int cch = 1; cch < 4; cch++)
            if (bva[cch] > bv) { bv = bva[cch]; bj = bja[cch]; }

        unsigned vb = __float_as_uint(bv);
        unsigned mx = redux_max_u32(vb);
        int cand = (vb == mx) ? (tid + bj * 128) : 0x7FFFFFFF;
        int mn = redux_min_s32(cand);
        if (lane == 0)
            s_key[buf][warp] = ((unsigned long long)mx << 32) |
                               (unsigned long long)(0xFFFFFFFFu - (unsigned)mn);
        __syncthreads();
        unsigned long long k0 = s_key[buf][0], k1 = s_key[buf][1];
        unsigned long long k2 = s_key[buf][2], k3 = s_key[buf][3];
        unsigned long long ba = (k0 > k1) ? k0 : k1;
        unsigned long long bb2 = (k2 > k3) ? k2 : k3;
        unsigned long long best = (ba > bb2) ? ba : bb2;
        int widx = (int)(0xFFFFFFFFu - (unsigned)(best & 0xFFFFFFFFull));
        cx = sx[widx]; cy = sy[widx]; cz = sz[widx];
        buf ^= 1;
    }
}

// ---------------- ball query: one warp per center ----------------
__global__ void __launch_bounds__(256) bq_kernel(const float* __restrict__ xyz) {
    int gw = (blockIdx.x * blockDim.x + threadIdx.x) >> 5;
    int lane = threadIdx.x & 31;
    int b = gw >> 10, s = gw & 1023;
    float4 c = d_newxyz[b * SS + s];
    const float* xb = xyz + b * 3 * NN;
    const float* nb = d_norm + b * NN;
    int* og = d_gidx + (b * SS + s) * KK;
    int cnt = 0, first = -1;
    for (int base = 0; base < NN; base += 32) {
        int n = base + lane;
        float dot = __fadd_rn(__fadd_rn(__fmul_rn(xb[n], c.x), __fmul_rn(xb[NN + n], c.y)),
                              __fmul_rn(xb[2 * NN + n], c.z));
        float sq = __fadd_rn(c.w, nb[n]) - 2.f * dot;
        bool ok = !(sq > 0.04f);
        unsigned m = __ballot_sync(0xffffffffu, ok);
        if (first < 0 && m) first = base + __ffs(m) - 1;
        if (ok) {
            int slot = cnt + __popc(m & ((1u << lane) - 1u));
            if (slot < KK) og[slot] = n;
        }
        cnt += __popc(m);
        if (cnt >= KK) break;
    }
    if (cnt < KK) {
        for (int k = cnt + lane; k < KK; k += 32) og[k] = first;
    }
}

// ---------------- layer0: gather + linear(6->64) + stats ----------------
__global__ void __launch_bounds__(256) layer0_kernel(const float* __restrict__ xyz,
                                                     const float* __restrict__ pts,
                                                     const float* __restrict__ w0,
                                                     const float* __restrict__ b0) {
    __shared__ float swT[6 * 64];
    __shared__ float sfeat[64 * 6];
    __shared__ float ssum[256], ssq[256];
    int t = threadIdx.x;
    for (int i = t; i < 384; i += 256) { int c = i >> 6, o = i & 63; swT[i] = w0[o * 6 + c]; }
    if (t < 64) {
        int rowg = blockIdx.x * 64 + t;
        int b = rowg >> 15, s = (rowg >> 5) & 1023;
        int n = d_gidx[rowg];
        float4 c4 = d_newxyz[b * SS + s];
        const float* xb = xyz + b * 3 * NN;
        const float* pb = pts + b * 3 * NN;
        sfeat[t * 6 + 0] = xb[n] - c4.x;
        sfeat[t * 6 + 1] = xb[NN + n] - c4.y;
        sfeat[t * 6 + 2] = xb[2 * NN + n] - c4.z;
        sfeat[t * 6 + 3] = pb[n];
        sfeat[t * 6 + 4] = pb[NN + n];
        sfeat[t * 6 + 5] = pb[2 * NN + n];
    }
    __syncthreads();
    int o = t & 63, grp = t >> 6;
    float bias = b0[o];
    float lsum = 0.f, lsq = 0.f;
    int base = blockIdx.x * 64;
#pragma unroll 4
    for (int i = 0; i < 16; i++) {
        int r = grp * 16 + i;
        float acc = bias;
#pragma unroll
        for (int c = 0; c < 6; c++) acc = fmaf(sfeat[r * 6 + c], swT[c * 64 + o], acc);
        d_z0[(size_t)(base + r) * 64 + o] = acc;
        lsum += acc; lsq = fmaf(acc, acc, lsq);
    }
    ssum[t] = lsum; ssq[t] = lsq; __syncthreads();
    if (t < 64) {
        float a = ssum[t] + ssum[t + 64] + ssum[t + 128] + ssum[t + 192];
        float q = ssq[t] + ssq[t + 64] + ssq[t + 128] + ssq[t + 192];
        atomicAdd(&d_sum[o], a); atomicAdd(&d_sumsq[o], q);
    }
}

__global__ void finalize_kernel(const float* __restrict__ g, const float* __restrict__ be, int l) {
    int o = threadIdx.x;
    float inv = 1.f / (float)ROWS;
    float mean = d_sum[l * 128 + o] * inv;
    float var = d_sumsq[l * 128 + o] * inv - mean * mean;
    float r = rsqrtf(var + 1e-5f);
    float scv = r * g[o];
    d_scale[l * 128 + o] = scv;
    d_shift[l * 128 + o] = fmaf(-mean, scv, be[o]);
}

// ================= layer1: tf32 MMA, M-tile 256, N=64 =================
// smem: sA 256*36 float2 (18432 f), sB 32*68 float2 (4352 f), stats 128 f
#define L1_A_F (256*36*2)
#define L1_B_F (32*68*2)
#define L1_SMEM ((L1_A_F + L1_B_F + 128) * 4)
__global__ void __launch_bounds__(256) layer1_kernel(const float* __restrict__ w1,
                                                     const float* __restrict__ b1) {
    extern __shared__ float sm[];
    float* sA = sm;
    float* sB = sm + L1_A_F;
    float* s_sum = sB + L1_B_F;
    float* s_sq  = s_sum + 64;
    int t = threadIdx.x;
    int lane = t & 31, w = t >> 5;
    if (t < 128) { s_sum[t & 63] = 0.f; s_sq[t & 63] = 0.f; }  // t<64 sum, 64..127 sq
    if (t < 64) s_sum[t] = 0.f; else if (t < 128) s_sq[t - 64] = 0.f;

    // weights: sB2[(ks*4+tg)*68 + o] = {w[ks*8+tg][o-col? no: w1[o][c]], ...}
    for (int i = t; i < 4096; i += 256) {
        int o = i >> 6, c = i & 63;
        int ks = c >> 3, tg = c & 3, half = (c >> 2) & 1;
        sB[2 * ((ks * 4 + tg) * 68 + o) + half] = tf32r(w1[i]);
    }
    // A tile: BN0+ReLU from d_z0
    size_t base = (size_t)blockIdx.x * 256;
    {
        int cg = t & 7, rgrp = t >> 3;
        int c0 = cg * 8;
        float sc[8], sh[8];
#pragma unroll
        for (int i = 0; i < 8; i++) { sc[i] = d_scale[c0 + i]; sh[i] = d_shift[c0 + i]; }
#pragma unroll
        for (int j = 0; j < 8; j++) {
            int row = rgrp + 32 * j;
            const float4 v1 = *(const float4*)(d_z0 + (base + row) * 64 + c0);
            const float4 v2 = *(const float4*)(d_z0 + (base + row) * 64 + c0 + 4);
            float lo[4] = {v1.x, v1.y, v1.z, v1.w};
            float hi[4] = {v2.x, v2.y, v2.z, v2.w};
#pragma unroll
            for (int i = 0; i < 4; i++) {
                float a = tf32r(fmaxf(0.f, fmaf(lo[i], sc[i], sh[i])));
                float bqv = tf32r(fmaxf(0.f, fmaf(hi[i], sc[i + 4], sh[i + 4])));
                sA[2 * (row * 36 + cg * 4 + i)] = a;
                sA[2 * (row * 36 + cg * 4 + i) + 1] = bqv;
            }
        }
    }
    int g = lane >> 2, tg = lane & 3;
    int row0 = w * 32;
    float acc[2][8][4];
#pragma unroll
    for (int ng = 0; ng < 8; ng++) {
        int c0 = ng * 8 + 2 * tg;
        float bz0 = b1[c0], bz1 = b1[c0 + 1];
#pragma unroll
        for (int r2 = 0; r2 < 2; r2++) {
            acc[r2][ng][0] = bz0; acc[r2][ng][1] = bz1;
            acc[r2][ng][2] = bz0; acc[r2][ng][3] = bz1;
        }
    }
    __syncthreads();
    const float2* sA2 = (const float2*)sA;
    const float2* sB2 = (const float2*)sB;
#pragma unroll
    for (int ks = 0; ks < 8; ks++) {
        float2 a0p0 = sA2[(row0 + g) * 36 + ks * 4 + tg];
        float2 a1p0 = sA2[(row0 + 8 + g) * 36 + ks * 4 + tg];
        float2 a0p1 = sA2[(row0 + 16 + g) * 36 + ks * 4 + tg];
        float2 a1p1 = sA2[(row0 + 24 + g) * 36 + ks * 4 + tg];
#pragma unroll
        for (int ng = 0; ng < 8; ng++) {
            float2 bp = sB2[(ks * 4 + tg) * 68 + ng * 8 + g];
            unsigned b0u = __float_as_uint(bp.x), b1u = __float_as_uint(bp.y);
            mma_tf32(acc[0][ng][0], acc[0][ng][1], acc[0][ng][2], acc[0][ng][3],
                     __float_as_uint(a0p0.x), __float_as_uint(a1p0.x),
                     __float_as_uint(a0p0.y), __float_as_uint(a1p0.y), b0u, b1u);
            mma_tf32(acc[1][ng][0], acc[1][ng][1], acc[1][ng][2], acc[1][ng][3],
                     __float_as_uint(a0p1.x), __float_as_uint(a1p1.x),
                     __float_as_uint(a0p1.y), __float_as_uint(a1p1.y), b0u, b1u);
        }
    }
    // store z1 + stats
#pragma unroll
    for (int ng = 0; ng < 8; ng++) {
        int c0 = ng * 8 + 2 * tg;
        float s0 = 0.f, q0 = 0.f, s1 = 0.f, q1 = 0.f;
#pragma unroll
        for (int r2 = 0; r2 < 2; r2++) {
            size_t row = base + row0 + r2 * 16 + g;
            float d0 = acc[r2][ng][0], d1 = acc[r2][ng][1];
            float d2 = acc[r2][ng][2], d3 = acc[r2][ng][3];
            *(float2*)(d_z1 + row * 64 + c0) = make_float2(d0, d1);
            *(float2*)(d_z1 + (row + 8) * 64 + c0) = make_float2(d2, d3);
            s0 += d0 + d2; s1 += d1 + d3;
            q0 = fmaf(d0, d0, fmaf(d2, d2, q0));
            q1 = fmaf(d1, d1, fmaf(d3, d3, q1));
        }
#pragma unroll
        for (int off = 16; off >= 4; off >>= 1) {
            s0 += __shfl_down_sync(0xffffffffu, s0, off);
            s1 += __shfl_down_sync(0xffffffffu, s1, off);
            q0 += __shfl_down_sync(0xffffffffu, q0, off);
            q1 += __shfl_down_sync(0xffffffffu, q1, off);
        }
        if (lane < 4) {
            int cc = ng * 8 + 2 * lane;
            atomicAdd(&s_sum[cc], s0); atomicAdd(&s_sum[cc + 1], s1);
            atomicAdd(&s_sq[cc], q0);  atomicAdd(&s_sq[cc + 1], q1);
        }
    }
    __syncthreads();
    if (t < 64) {
        atomicAdd(&d_sum[128 + t], s_sum[t]);
        atomicAdd(&d_sumsq[128 + t], s_sq[t]);
    }
}

// ================= layer2 common: tf32 MMA, M-tile 128, N=128 =================
#define L2_A_F (128*36*2)
#define L2_B_F (32*132*2)
#define L2S_SMEM ((L2_A_F + L2_B_F + 256) * 4)
#define L2P_SMEM ((L2_A_F + L2_B_F + 256 + 1024) * 4)

__device__ __forceinline__ void l2_fill_and_mma(float* sA, float* sB,
                                                const float* __restrict__ w2,
                                                const float* __restrict__ b2,
                                                size_t base, int t, float acc[16][4]) {
    int lane = t & 31, w = t >> 5;
    for (int i = t; i < 8192; i += 256) {
        int o = i >> 6, c = i & 63;
        int ks = c >> 3, tg = c & 3, half = (c >> 2) & 1;
        sB[2 * ((ks * 4 + tg) * 132 + o) + half] = tf32r(w2[i]);
    }
    {
        int cg = t & 7, rgrp = t >> 3;
        int c0 = cg * 8;
        float sc[8], sh[8];
#pragma unroll
        for (int i = 0; i < 8; i++) { sc[i] = d_scale[128 + c0 + i]; sh[i] = d_shift[128 + c0 + i]; }
#pragma unroll
        for (int j = 0; j < 4; j++) {
            int row = rgrp + 32 * j;
            const float4 v1 = *(const float4*)(d_z1 + (base + row) * 64 + c0);
            const float4 v2 = *(const float4*)(d_z1 + (base + row) * 64 + c0 + 4);
            float lo[4] = {v1.x, v1.y, v1.z, v1.w};
            float hi[4] = {v2.x, v2.y, v2.z, v2.w};
#pragma unroll
            for (int i = 0; i < 4; i++) {
                sA[2 * (row * 36 + cg * 4 + i)]     = tf32r(fmaxf(0.f, fmaf(lo[i], sc[i], sh[i])));
                sA[2 * (row * 36 + cg * 4 + i) + 1] = tf32r(fmaxf(0.f, fmaf(hi[i], sc[i + 4], sh[i + 4])));
            }
        }
    }
    int g = lane >> 2, tg = lane & 3;
    int row0 = w * 16;
#pragma unroll
    for (int ng = 0; ng < 16; ng++) {
        int c0 = ng * 8 + 2 * tg;
        float bz0 = b2[c0], bz1 = b2[c0 + 1];
        acc[ng][0] = bz0; acc[ng][1] = bz1; acc[ng][2] = bz0; acc[ng][3] = bz1;
    }
    __syncthreads();
    const float2* sA2 = (const float2*)sA;
    const float2* sB2 = (const float2*)sB;
#pragma unroll
    for (int ks = 0; ks < 8; ks++) {
        float2 a0p = sA2[(row0 + g) * 36 + ks * 4 + tg];
        float2 a1p = sA2[(row0 + 8 + g) * 36 + ks * 4 + tg];
        unsigned a0 = __float_as_uint(a0p.x), a1 = __float_as_uint(a1p.x);
        unsigned a2 = __float_as_uint(a0p.y), a3 = __float_as_uint(a1p.y);
#pragma unroll
        for (int ng = 0; ng < 16; ng++) {
            float2 bp = sB2[(ks * 4 + tg) * 132 + ng * 8 + g];
            mma_tf32(acc[ng][0], acc[ng][1], acc[ng][2], acc[ng][3],
                     a0, a1, a2, a3, __float_as_uint(bp.x), __float_as_uint(bp.y));
        }
    }
}

// ---- l2stats: mma + channel stats only (no z2 store) ----
__global__ void __launch_bounds__(256) l2stats_kernel(const float* __restrict__ w2,
                                                      const float* __restrict__ b2) {
    extern __shared__ float sm[];
    float* sA = sm;
    float* sB = sm + L2_A_F;
    float* s_sum = sB + L2_B_F;
    float* s_sq  = s_sum + 128;
    int t = threadIdx.x;
    int lane = t & 31;
    if (t < 128) { s_sum[t] = 0.f; s_sq[t] = 0.f; }
    float acc[16][4];
    size_t base = (size_t)blockIdx.x * 128;
    l2_fill_and_mma(sA, sB, w2, b2, base, t, acc);
#pragma unroll
    for (int ng = 0; ng < 16; ng++) {
        float d0 = acc[ng][0], d1 = acc[ng][1], d2 = acc[ng][2], d3 = acc[ng][3];
        float s0 = d0 + d2, s1 = d1 + d3;
        float q0 = fmaf(d0, d0, d2 * d2), q1 = fmaf(d1, d1, d3 * d3);
#pragma unroll
        for (int off = 16; off >= 4; off >>= 1) {
            s0 += __shfl_down_sync(0xffffffffu, s0, off);
            s1 += __shfl_down_sync(0xffffffffu, s1, off);
            q0 += __shfl_down_sync(0xffffffffu, q0, off);
            q1 += __shfl_down_sync(0xffffffffu, q1, off);
        }
        if (lane < 4) {
            int cc = ng * 8 + 2 * lane;
            atomicAdd(&s_sum[cc], s0); atomicAdd(&s_sum[cc + 1], s1);
            atomicAdd(&s_sq[cc], q0);  atomicAdd(&s_sq[cc + 1], q1);
        }
    }
    __syncthreads();
    if (t < 128) {
        atomicAdd(&d_sum[256 + t], s_sum[t]);
        atomicAdd(&d_sumsq[256 + t], s_sq[t]);
    }
}

// ---- l2pool: recompute mma + BN2+ReLU + maxpool over K=32 + transpose out ----
__global__ void __launch_bounds__(256) l2pool_kernel(const float* __restrict__ w2,
                                                     const float* __restrict__ b2,
                                                     float* __restrict__ out) {
    extern __shared__ float sm[];
    float* sA = sm;
    float* sB = sm + L2_A_F;
    float* s_sc = sB + L2_B_F;
    float* s_sh = s_sc + 128;
    float* pmax = s_sh + 128;      // [8][128]
    int t = threadIdx.x;
    int lane = t & 31, w = t >> 5;
    if (t < 128) { s_sc[t] = d_scale[256 + t]; s_sh[t] = d_shift[256 + t]; }
    float acc[16][4];
    size_t base = (size_t)blockIdx.x * 128;
    l2_fill_and_mma(sA, sB, w2, b2, base, t, acc);
#pragma unroll
    for (int ng = 0; ng < 16; ng++) {
        int tg = lane & 3;
        int c0 = ng * 8 + 2 * tg;
        float sc0 = s_sc[c0], sh0 = s_sh[c0];
        float sc1 = s_sc[c0 + 1], sh1 = s_sh[c0 + 1];
        float m0 = fmaxf(fmaxf(0.f, fmaf(acc[ng][0], sc0, sh0)),
                         fmaxf(0.f, fmaf(acc[ng][2], sc0, sh0)));
        float m1 = fmaxf(fmaxf(0.f, fmaf(acc[ng][1], sc1, sh1)),
                         fmaxf(0.f, fmaf(acc[ng][3], sc1, sh1)));
#pragma unroll
        for (int off = 16; off >= 4; off >>= 1) {
            m0 = fmaxf(m0, __shfl_down_sync(0xffffffffu, m0, off));
            m1 = fmaxf(m1, __shfl_down_sync(0xffffffffu, m1, off));
        }
        if (lane < 4) {
            int cc = ng * 8 + 2 * lane;
            pmax[w * 128 + cc] = m0;
            pmax[w * 128 + cc + 1] = m1;
        }
    }
    __syncthreads();
    if (t < 128) {
        int sglob = blockIdx.x * 4;                 // 4 s per block
        int b = sglob >> 10, s_in = sglob & 1023;
        float4 v;
        v.x = fmaxf(pmax[0 * 128 + t], pmax[1 * 128 + t]);
        v.y = fmaxf(pmax[2 * 128 + t], pmax[3 * 128 + t]);
        v.z = fmaxf(pmax[4 * 128 + t], pmax[5 * 128 + t]);
        v.w = fmaxf(pmax[6 * 128 + t], pmax[7 * 128 + t]);
        *(float4*)(out + (size_t)BB * 3 * SS + (size_t)b * 128 * SS + (size_t)t * SS + s_in) = v;
    }
}

extern "C" void kernel_launch(void* const* d_in, const int* in_sizes, int n_in,
                              void* d_out, int out_size) {
    (void)in_sizes; (void)n_in; (void)out_size;
    const float* xyz = (const float*)d_in[0];
    const float* pts = (const float*)d_in[1];
    const float* w0 = (const float*)d_in[2];  const float* b0 = (const float*)d_in[3];
    const float* g0 = (const float*)d_in[4];  const float* be0 = (const float*)d_in[5];
    const float* w1 = (const float*)d_in[6];  const float* b1 = (const float*)d_in[7];
    const float* g1 = (const float*)d_in[8];  const float* be1 = (const float*)d_in[9];
    const float* w2 = (const float*)d_in[10]; const float* b2 = (const float*)d_in[11];
    const float* g2 = (const float*)d_in[12]; const float* be2 = (const float*)d_in[13];
    float* out = (float*)d_out;

    cudaFuncSetAttribute(layer1_kernel, cudaFuncAttributeMaxDynamicSharedMemorySize, L1_SMEM);
    cudaFuncSetAttribute(l2stats_kernel, cudaFuncAttributeMaxDynamicSharedMemorySize, L2S_SMEM);
    cudaFuncSetAttribute(l2pool_kernel, cudaFuncAttributeMaxDynamicSharedMemorySize, L2P_SMEM);

    zero_kernel<<<1, 384>>>();
    fps_kernel<<<BB, 128>>>(xyz, out);
    bq_kernel<<<1024, 256>>>(xyz);
    layer0_kernel<<<ROWS / 64, 256>>>(xyz, pts, w0, b0);
    finalize_kernel<<<1, 64>>>(g0, be0, 0);
    layer1_kernel<<<ROWS / 256, 256, L1_SMEM>>>(w1, b1);
    finalize_kernel<<<1, 64>>>(g1, be1, 1);
    l2stats_kernel<<<ROWS / 128, 256, L2S_SMEM>>>(w2, b2);
    finalize_kernel<<<1, 128>>>(g2, be2, 2);
    l2pool_kernel<<<ROWS / 128, 256, L2P_SMEM>>>(w2, b2, out);
}